// round 7
// baseline (speedup 1.0000x reference)
#include <cuda_runtime.h>
#include <cstdint>

// out[n,m,q] = sum_d x[n,m,d] * W[sidx[n],d,q]
// x: [16384,64,128] f32, sidx: [16384] i32/i64, W: [8,128,128] f32
// Route: species-grouped persistent CTAs + mma.sync.m16n8k8 TF32.
// x fed as RAW fp32 bits (HW uses top 19 bits); W pre-rounded to tf32 (RN).

#define NSAMP  16384
#define NCOMP  64
#define DIN    128
#define DOUT   128
#define NSPEC  8
#define SLOTS  19
#define GRIDSZ (NSPEC * SLOTS)      // 152 = GB300 SM count

#define KPADF  136                  // padded k-stride in floats (544 B rows)
#define SBYTES (KPADF * 4)          // 544
#define WELEMS (DOUT * KPADF)       // 17408 fp32 per W image

// ---------------- device scratch ----------------
__device__ int g_sidx[NSAMP];
__device__ int g_cnt[NSPEC];
__device__ int g_off[NSPEC];
__device__ int g_fill[NSPEC];
__device__ int g_sorted[NSAMP];
__device__ int g_is64;
__device__ __align__(16) uint32_t g_wt[NSPEC][WELEMS];  // Wt[q][k] tf32-RN bits

// ---------------- smem layout (bytes) ----------------
#define SM_W   0
#define SM_X0  (SM_W + WELEMS * 4)              // 69632
#define SM_X1  (SM_X0 + NCOMP * SBYTES)         // 104448
#define SM_TOTAL (SM_X1 + NCOMP * SBYTES)       // 139264

// ---------------- PTX helpers ----------------
__device__ __forceinline__ uint32_t smem_u32(const void* p) {
    uint32_t a;
    asm("{ .reg .u64 t; cvta.to.shared.u64 t, %1; cvt.u32.u64 %0, t; }"
        : "=r"(a) : "l"(p));
    return a;
}
__device__ __forceinline__ void cp16(uint32_t dst, const void* src) {
    asm volatile("cp.async.cg.shared.global [%0], [%1], 16;"
                 :: "r"(dst), "l"(src) : "memory");
}
__device__ __forceinline__ void cp_commit() {
    asm volatile("cp.async.commit_group;" ::: "memory");
}
__device__ __forceinline__ void cp_wait0() {
    asm volatile("cp.async.wait_group 0;" ::: "memory");
}
__device__ __forceinline__ void cp_wait1() {
    asm volatile("cp.async.wait_group 1;" ::: "memory");
}
__device__ __forceinline__ void ldsm4(uint32_t* r, uint32_t addr) {
    asm volatile("ldmatrix.sync.aligned.m8n8.x4.shared.b16 {%0,%1,%2,%3}, [%4];"
                 : "=r"(r[0]), "=r"(r[1]), "=r"(r[2]), "=r"(r[3]) : "r"(addr));
}
__device__ __forceinline__ void mma_tf32(float* d, const uint32_t* a,
                                         const uint32_t* b) {
    asm volatile(
        "mma.sync.aligned.m16n8k8.row.col.f32.tf32.tf32.f32 "
        "{%0,%1,%2,%3}, {%4,%5,%6,%7}, {%8,%9}, {%0,%1,%2,%3};"
        : "+f"(d[0]), "+f"(d[1]), "+f"(d[2]), "+f"(d[3])
        : "r"(a[0]), "r"(a[1]), "r"(a[2]), "r"(a[3]), "r"(b[0]), "r"(b[1]));
}
__device__ __forceinline__ uint32_t f2tf32_rn(float v) {
    uint32_t r;
    asm("cvt.rna.tf32.f32 %0, %1;" : "=r"(r) : "f"(v));
    return r;
}

// ---------------- prep kernels (decode/group proven in R2-R6) ----------------
__global__ void prep0_detect(const unsigned int* __restrict__ raw) {
    __shared__ int s_not64;
    int tid = threadIdx.x;
    if (tid == 0) s_not64 = 0;
    if (tid < NSPEC) { g_cnt[tid] = 0; g_fill[tid] = 0; }
    __syncthreads();
    int bad = 0;
    for (int w = tid * 2 + 1; w < NSAMP; w += 512)
        if (raw[w] != 0u) bad = 1;
    if (bad) atomicOr(&s_not64, 1);
    __syncthreads();
    if (tid == 0) g_is64 = (s_not64 == 0);
}
__global__ void prep1_decode_count(const unsigned int* __restrict__ raw) {
    int i = blockIdx.x * 256 + threadIdx.x;
    unsigned v = g_is64 ? raw[2 * i] : raw[i];
    if (v > 7u) v = 7u;
    g_sidx[i] = (int)v;
    atomicAdd(&g_cnt[v], 1);
}
__global__ void prep2_offsets() {
    int o = 0;
    for (int s = 0; s < NSPEC; s++) { g_off[s] = o; o += g_cnt[s]; }
}
__global__ void prep3_scatter() {
    int n = blockIdx.x * 256 + threadIdx.x;
    int s = g_sidx[n];
    int pos = atomicAdd(&g_fill[s], 1);
    g_sorted[g_off[s] + pos] = n;
}
// Wt[q][k] tf32(RN) bits, padded to KPADF (pads zero).
__global__ void prep4_wimg(const float* __restrict__ W) {
    int s = blockIdx.x;
    for (int e = threadIdx.x; e < WELEMS; e += blockDim.x) {
        int q = e / KPADF, k = e % KPADF;
        uint32_t b = 0;
        if (k < DIN) b = f2tf32_rn(W[s * DIN * DOUT + k * DOUT + q]);
        g_wt[s][q * KPADF + k] = b;
    }
}

// ---------------- main kernel ----------------
// 8 warps: wm = wid>>2 (two 32-row M tiles), wn = wid&3 (four 32-col N tiles).
__global__ __launch_bounds__(256, 1)
void mma_main(const float* __restrict__ x, float* __restrict__ out)
{
    extern __shared__ char smem[];
    const uint32_t sb = smem_u32(smem);
    const int tid  = threadIdx.x;
    const int lane = tid & 31;
    const int wid  = tid >> 5;
    const int wm   = wid >> 2;           // 0..1
    const int wn   = wid & 3;            // 0..3
    const int spec = blockIdx.x / SLOTS;
    const int slot = blockIdx.x % SLOTS;

    // ---- stage W image (68 KB tf32 bits) once: 4352 16B chunks ----
    {
        const uint32_t* wt = g_wt[spec];
        #pragma unroll
        for (int i = 0; i < 17; i++) {
            int idx = tid + i * 256;              // 0..4351
            cp16(sb + SM_W + idx * 16, wt + idx * 4);
        }
        cp_commit();
    }

    const int cnt = g_cnt[spec];
    const int off = g_off[spec];
    if (slot >= cnt) { cp_wait0(); return; }

    // ldmatrix addresses (b16-view of fp32 tiles)
    // A (x) 16x8 fp32 tile: m0 rows0-7 k0-3 | m1 rows8-15 k0-3 |
    //                       m2 rows0-7 k4-7 | m3 rows8-15 k4-7
    const int a_row  = lane & 15;
    const int a_boff = (lane >> 4) * 16;          // bytes
    // B (Wt) 8x8 fp32 tile pair: m0 n0-7 k0-3 | m1 n0-7 k4-7 |
    //                            m2 n0-7 k8-11 | m3 n0-7 k12-15 (2 ks groups)
    const int b_row  = lane & 7;
    const int b_boff = (lane >> 3) * 16;          // bytes

    uint32_t aOff[2];                             // offsets within x buffer
    #pragma unroll
    for (int mi = 0; mi < 2; mi++)
        aOff[mi] = (wm * 32 + mi * 16 + a_row) * SBYTES + a_boff;
    uint32_t bAddr[4];
    #pragma unroll
    for (int p = 0; p < 4; p++)
        bAddr[p] = sb + SM_W + (wn * 32 + p * 8 + b_row) * SBYTES + b_boff;

    // ---- prefetch first sample into X0 ----
    int n_cur = g_sorted[off + slot];
    {
        const float* xs = x + (size_t)n_cur * (NCOMP * DIN);
        #pragma unroll
        for (int i = 0; i < 8; i++) {
            int idx = tid + i * 256;              // 0..2047
            int row = idx >> 5, c16 = idx & 31;
            cp16(sb + SM_X0 + row * SBYTES + c16 * 16, xs + row * DIN + c16 * 4);
        }
        cp_commit();
    }

    int buf = 0;
    for (int j = slot; j < cnt; j += SLOTS) {
        const int jn = j + SLOTS;
        const int n_next = (jn < cnt) ? g_sorted[off + jn] : n_cur;
        {
            const uint32_t dst = sb + (buf ? SM_X0 : SM_X1);
            const float* xs = x + (size_t)n_next * (NCOMP * DIN);
            #pragma unroll
            for (int i = 0; i < 8; i++) {
                int idx = tid + i * 256;
                int row = idx >> 5, c16 = idx & 31;
                cp16(dst + row * SBYTES + c16 * 16, xs + row * DIN + c16 * 4);
            }
            cp_commit();
        }
        cp_wait1();                 // current buffer's copy complete
        __syncthreads();            // visible to all warps

        const uint32_t xb = sb + (buf ? SM_X1 : SM_X0);

        // ---- single-term tf32 MMA over K=128 (16 k8 groups, 2 per step) ----
        float acc[2][4][4];
        #pragma unroll
        for (int mi = 0; mi < 2; mi++)
            #pragma unroll
            for (int p = 0; p < 4; p++)
                #pragma unroll
                for (int e = 0; e < 4; e++) acc[mi][p][e] = 0.0f;

        #pragma unroll
        for (int k2 = 0; k2 < 8; k2++) {
            const uint32_t kb = k2 * 64;          // 16 fp32 = 64 B
            uint32_t A[2][2][4], B[4][4];
            #pragma unroll
            for (int mi = 0; mi < 2; mi++) {
                ldsm4(A[mi][0], xb + aOff[mi] + kb);        // ks even
                ldsm4(A[mi][1], xb + aOff[mi] + kb + 32);   // ks odd
            }
            #pragma unroll
            for (int p = 0; p < 4; p++)
                ldsm4(B[p], bAddr[p] + kb);       // {b0,b1} even | {b0,b1} odd
            #pragma unroll
            for (int h = 0; h < 2; h++)
                #pragma unroll
                for (int mi = 0; mi < 2; mi++)
                    #pragma unroll
                    for (int p = 0; p < 4; p++)
                        mma_tf32(acc[mi][p], A[mi][h], &B[p][2 * h]);
        }

        // ---- epilogue: direct STG.64 ----
        {
            const int r  = lane >> 2;
            const int c2 = 2 * (lane & 3);
            float* ob = out + (size_t)n_cur * (NCOMP * DOUT);
            #pragma unroll
            for (int mi = 0; mi < 2; mi++) {
                const int gm = wm * 32 + mi * 16 + r;
                #pragma unroll
                for (int p = 0; p < 4; p++) {
                    const int gq = wn * 32 + p * 8 + c2;
                    float* o = ob + gm * DOUT + gq;
                    *(float2*)o = make_float2(acc[mi][p][0], acc[mi][p][1]);
                    *(float2*)(o + 8 * DOUT) =
                        make_float2(acc[mi][p][2], acc[mi][p][3]);
                }
            }
        }
        __syncthreads();            // reads of this buffer done before reuse
        n_cur = n_next;
        buf ^= 1;
    }
    cp_wait0();
}

// ---------------- launch ----------------
extern "C" void kernel_launch(void* const* d_in, const int* in_sizes, int n_in,
                              void* d_out, int out_size)
{
    const float*        x    = nullptr;
    const unsigned int* sidx = nullptr;
    const float*        W    = nullptr;
    for (int i = 0; i < n_in; i++) {
        if      (in_sizes[i] == NSAMP * NCOMP * DIN) x    = (const float*)d_in[i];
        else if (in_sizes[i] == NSAMP)               sidx = (const unsigned int*)d_in[i];
        else if (in_sizes[i] == NSPEC * DIN * DOUT)  W    = (const float*)d_in[i];
    }
    float* out = (float*)d_out;

    prep0_detect<<<1, 256>>>(sidx);
    prep1_decode_count<<<NSAMP / 256, 256>>>(sidx);
    prep2_offsets<<<1, 1>>>();
    prep3_scatter<<<NSAMP / 256, 256>>>();
    prep4_wimg<<<NSPEC, 256>>>(W);

    cudaFuncSetAttribute(mma_main, cudaFuncAttributeMaxDynamicSharedMemorySize,
                         SM_TOTAL);
    mma_main<<<GRIDSZ, 256, SM_TOTAL>>>(x, out);
}

// round 8
// speedup vs baseline: 1.1326x; 1.1326x over previous
#include <cuda_runtime.h>
#include <cstdint>

// out[n,m,q] = sum_d x[n,m,d] * W[sidx[n],d,q]
// x: [16384,64,128] f32, sidx: [16384] i32/i64, W: [8,128,128] f32
// Route: species-grouped persistent CTAs + mma.sync.m16n8k16 bf16 3-term
// fp32 emulation, with software-pipelined conversion (convert sample t+1
// overlapped with MMA of sample t; one barrier per iteration).

#define NSAMP  16384
#define NCOMP  64
#define DIN    128
#define DOUT   128
#define NSPEC  8
#define SLOTS  19
#define GRIDSZ (NSPEC * SLOTS)     // 152 = GB300 SM count

#define KPAD   136                 // padded k-stride (bank-rotation 4i mod 32)
#define WELEMS (DOUT * KPAD)       // 17408 bf16 per W image
#define CONVB  (NCOMP * KPAD * 2)  // 17408 B: one xhi (or xlo) image

// ---------------- device scratch ----------------
__device__ int g_sidx[NSAMP];
__device__ int g_cnt[NSPEC];
__device__ int g_off[NSPEC];
__device__ int g_fill[NSPEC];
__device__ int g_sorted[NSAMP];
__device__ int g_is64;
__device__ __align__(16) uint16_t g_whi[NSPEC][WELEMS];  // Wt[q][k] bf16 hi
__device__ __align__(16) uint16_t g_wlo[NSPEC][WELEMS];  // Wt[q][k] bf16 lo

// ---------------- smem layout (bytes) ----------------
#define SM_WHI   0
#define SM_WLO   (SM_WHI + WELEMS * 2)        // 34816
#define SM_CONV0 (SM_WLO + WELEMS * 2)        // 69632  (xhi0 | xlo0)
#define SM_CONV1 (SM_CONV0 + 2 * CONVB)       // 104448 (xhi1 | xlo1)
#define SM_RAW0  (SM_CONV1 + 2 * CONVB)       // 139264
#define SM_RAW1  (SM_RAW0 + 32768)            // 172032
#define SM_TOTAL (SM_RAW1 + 32768)            // 204800

// ---------------- PTX helpers ----------------
__device__ __forceinline__ uint32_t smem_u32(const void* p) {
    uint32_t a;
    asm("{ .reg .u64 t; cvta.to.shared.u64 t, %1; cvt.u32.u64 %0, t; }"
        : "=r"(a) : "l"(p));
    return a;
}
__device__ __forceinline__ void cp16(uint32_t dst, const void* src) {
    asm volatile("cp.async.cg.shared.global [%0], [%1], 16;"
                 :: "r"(dst), "l"(src) : "memory");
}
__device__ __forceinline__ void cp_commit() {
    asm volatile("cp.async.commit_group;" ::: "memory");
}
__device__ __forceinline__ void cp_wait0() {
    asm volatile("cp.async.wait_group 0;" ::: "memory");
}
__device__ __forceinline__ void cp_wait1() {
    asm volatile("cp.async.wait_group 1;" ::: "memory");
}
__device__ __forceinline__ void ldsm4(uint32_t* r, uint32_t addr) {
    asm volatile("ldmatrix.sync.aligned.m8n8.x4.shared.b16 {%0,%1,%2,%3}, [%4];"
                 : "=r"(r[0]), "=r"(r[1]), "=r"(r[2]), "=r"(r[3]) : "r"(addr));
}
__device__ __forceinline__ void mma_bf16(float* d, const uint32_t* a,
                                         const uint32_t* b) {
    asm volatile(
        "mma.sync.aligned.m16n8k16.row.col.f32.bf16.bf16.f32 "
        "{%0,%1,%2,%3}, {%4,%5,%6,%7}, {%8,%9}, {%0,%1,%2,%3};"
        : "+f"(d[0]), "+f"(d[1]), "+f"(d[2]), "+f"(d[3])
        : "r"(a[0]), "r"(a[1]), "r"(a[2]), "r"(a[3]), "r"(b[0]), "r"(b[1]));
}
__device__ __forceinline__ uint32_t pack_bf16x2(float fh, float fl) {
    uint32_t r;
    asm("cvt.rn.bf16x2.f32 %0, %1, %2;" : "=r"(r) : "f"(fh), "f"(fl));
    return r;
}

// ---------------- prep kernels (proven R2-R6) ----------------
__global__ void prep0_detect(const unsigned int* __restrict__ raw) {
    __shared__ int s_not64;
    int tid = threadIdx.x;
    if (tid == 0) s_not64 = 0;
    if (tid < NSPEC) { g_cnt[tid] = 0; g_fill[tid] = 0; }
    __syncthreads();
    int bad = 0;
    for (int w = tid * 2 + 1; w < NSAMP; w += 512)
        if (raw[w] != 0u) bad = 1;
    if (bad) atomicOr(&s_not64, 1);
    __syncthreads();
    if (tid == 0) g_is64 = (s_not64 == 0);
}
__global__ void prep1_decode_count(const unsigned int* __restrict__ raw) {
    int i = blockIdx.x * 256 + threadIdx.x;
    unsigned v = g_is64 ? raw[2 * i] : raw[i];
    if (v > 7u) v = 7u;
    g_sidx[i] = (int)v;
    atomicAdd(&g_cnt[v], 1);
}
__global__ void prep2_offsets() {
    int o = 0;
    for (int s = 0; s < NSPEC; s++) { g_off[s] = o; o += g_cnt[s]; }
}
__global__ void prep3_scatter() {
    int n = blockIdx.x * 256 + threadIdx.x;
    int s = g_sidx[n];
    int pos = atomicAdd(&g_fill[s], 1);
    g_sorted[g_off[s] + pos] = n;
}
__global__ void prep4_wimg(const float* __restrict__ W) {
    int s = blockIdx.x;
    for (int e = threadIdx.x; e < WELEMS; e += blockDim.x) {
        int q = e / KPAD, k = e % KPAD;
        uint16_t hb = 0, lb = 0;
        if (k < DIN) {
            float v = W[s * DIN * DOUT + k * DOUT + q];
            uint32_t p = pack_bf16x2(v, 0.0f);
            hb = (uint16_t)(p >> 16);
            float hf = __uint_as_float(((uint32_t)hb) << 16);
            uint32_t pl = pack_bf16x2(v - hf, 0.0f);
            lb = (uint16_t)(pl >> 16);
        }
        g_whi[s][q * KPAD + k] = hb;
        g_wlo[s][q * KPAD + k] = lb;
    }
}

// ---------------- conversion: raw fp32 buffer -> bf16 hi/lo images ----------
__device__ __forceinline__ void convert_x(char* smem, int rawOff, int convOff,
                                          int tid)
{
    const float* rawf = (const float*)(smem + rawOff);
    #pragma unroll
    for (int jj = 0; jj < 8; jj++) {
        const int f   = jj * 1024 + tid * 4;
        const int row = f >> 7;
        const int k   = f & 127;
        float4 v = *(const float4*)(rawf + f);

        uint32_t h01 = pack_bf16x2(v.y, v.x);
        uint32_t h23 = pack_bf16x2(v.w, v.z);
        float h0 = __uint_as_float(h01 << 16);
        float h1 = __uint_as_float(h01 & 0xFFFF0000u);
        float h2 = __uint_as_float(h23 << 16);
        float h3 = __uint_as_float(h23 & 0xFFFF0000u);
        uint32_t l01 = pack_bf16x2(v.y - h1, v.x - h0);
        uint32_t l23 = pack_bf16x2(v.w - h3, v.z - h2);

        const int boff = (row * KPAD + k) * 2;
        *(uint2*)(smem + convOff + boff)         = make_uint2(h01, h23);
        *(uint2*)(smem + convOff + CONVB + boff) = make_uint2(l01, l23);
    }
}

// ---------------- main kernel ----------------
__global__ __launch_bounds__(256, 1)
void mma_main(const float* __restrict__ x, float* __restrict__ out)
{
    extern __shared__ char smem[];
    const uint32_t sb = smem_u32(smem);
    const int tid  = threadIdx.x;
    const int lane = tid & 31;
    const int wid  = tid >> 5;
    const int wm   = wid >> 2;           // 0..1  (m tile 32)
    const int wn   = wid & 3;            // 0..3  (n tile 32)
    const int spec = blockIdx.x / SLOTS;
    const int slot = blockIdx.x % SLOTS;

    // ---- stage W images (hi+lo bf16, 68 KB) once: group gW ----
    {
        const uint16_t* whi = g_whi[spec];
        const uint16_t* wlo = g_wlo[spec];
        #pragma unroll
        for (int i = 0; i < 9; i++) {
            int idx = tid + i * 256;
            if (idx < WELEMS / 8) {
                cp16(sb + SM_WHI + idx * 16, whi + idx * 8);
                cp16(sb + SM_WLO + idx * 16, wlo + idx * 8);
            }
        }
        cp_commit();
    }

    const int cnt = g_cnt[spec];
    const int off = g_off[spec];
    if (slot >= cnt) { cp_wait0(); return; }

    const int T = (cnt - slot + SLOTS - 1) / SLOTS;   // iterations for this slot

    // ldmatrix lane address components
    const int a_row  = (lane & 15);
    const int a_koff = (lane >> 4) * 8;
    const int b_row  = ((lane >> 4) * 8) + (lane & 7);
    const int b_koff = ((lane >> 3) & 1) * 8;

    uint32_t aOff[2];                    // relative to conv buffer base (xhi)
    #pragma unroll
    for (int mi = 0; mi < 2; mi++)
        aOff[mi] = ((wm * 32 + mi * 16 + a_row) * KPAD + a_koff) * 2;
    uint32_t bAddr[2];
    #pragma unroll
    for (int p = 0; p < 2; p++)
        bAddr[p] = sb + SM_WHI + ((wn * 32 + p * 16 + b_row) * KPAD + b_koff) * 2;
    const uint32_t WLO_OFF = SM_WLO - SM_WHI;

    // ---- prologue: raw(n0) -> RAW0 (g0), raw(n1) -> RAW1 (g1) ----
    int n0 = g_sorted[off + slot];
    int n1 = (slot + SLOTS < cnt) ? g_sorted[off + slot + SLOTS] : n0;
    {
        const float* xs = x + (size_t)n0 * (NCOMP * DIN);
        #pragma unroll
        for (int i = 0; i < 8; i++)
            cp16(sb + SM_RAW0 + (tid + i * 256) * 16, xs + (tid + i * 256) * 4);
        cp_commit();
        const float* xs1 = x + (size_t)n1 * (NCOMP * DIN);
        #pragma unroll
        for (int i = 0; i < 8; i++)
            cp16(sb + SM_RAW1 + (tid + i * 256) * 16, xs1 + (tid + i * 256) * 4);
        cp_commit();
    }
    cp_wait1();                          // gW, g0 complete (g1 may fly)
    convert_x(smem, SM_RAW0, SM_CONV0, tid);
    __syncthreads();                     // conv0 + W visible to all

    int n_cur = n0, n_next = n1;

    for (int t = 0; t < T; t++) {
        // ---- issue cp of sample t+2 into raw[t&1] (group g_{t+2}) ----
        const int i2 = off + slot + (t + 2) * SLOTS;
        const int n_next2 = (slot + (t + 2) * SLOTS < cnt) ? g_sorted[i2] : n_next;
        {
            const uint32_t dst = sb + ((t & 1) ? SM_RAW1 : SM_RAW0);
            const float* xs = x + (size_t)n_next2 * (NCOMP * DIN);
            #pragma unroll
            for (int i = 0; i < 8; i++)
                cp16(dst + (tid + i * 256) * 16, xs + (tid + i * 256) * 4);
            cp_commit();
        }
        cp_wait1();                      // raw(t+1) ready (newest group pending)

        // ---- convert sample t+1 into conv[(t+1)&1]  (no barrier before mma!)
        convert_x(smem, ((t & 1) ? SM_RAW0 : SM_RAW1),
                  (((t + 1) & 1) ? SM_CONV1 : SM_CONV0), tid);

        // ---- 3-term bf16 mma on sample t from conv[t&1] ----
        const uint32_t xb = sb + ((t & 1) ? SM_CONV1 : SM_CONV0);
        float acc[2][4][4];
        #pragma unroll
        for (int mi = 0; mi < 2; mi++)
            #pragma unroll
            for (int ni = 0; ni < 4; ni++)
                #pragma unroll
                for (int e = 0; e < 4; e++) acc[mi][ni][e] = 0.0f;

        #pragma unroll
        for (int ks = 0; ks < 8; ks++) {
            const uint32_t kb = ks * 32;
            uint32_t AH[2][4], AL[2][4], BH[2][4], BL[2][4];
            #pragma unroll
            for (int mi = 0; mi < 2; mi++) {
                ldsm4(AH[mi], xb + aOff[mi] + kb);
                ldsm4(AL[mi], xb + CONVB + aOff[mi] + kb);
            }
            #pragma unroll
            for (int p = 0; p < 2; p++) {
                ldsm4(BH[p], bAddr[p] + kb);
                ldsm4(BL[p], bAddr[p] + WLO_OFF + kb);
            }
            #pragma unroll
            for (int mi = 0; mi < 2; mi++)
                #pragma unroll
                for (int p = 0; p < 2; p++)
                    #pragma unroll
                    for (int h = 0; h < 2; h++) {
                        const int ni = p * 2 + h;
                        mma_bf16(acc[mi][ni], AH[mi], &BH[p][2 * h]);
                        mma_bf16(acc[mi][ni], AH[mi], &BL[p][2 * h]);
                        mma_bf16(acc[mi][ni], AL[mi], &BH[p][2 * h]);
                    }
        }

        // ---- epilogue: direct STG.64 for sample t ----
        {
            const int r  = lane >> 2;
            const int c2 = 2 * (lane & 3);
            float* ob = out + (size_t)n_cur * (NCOMP * DOUT);
            #pragma unroll
            for (int mi = 0; mi < 2; mi++) {
                const int gm = wm * 32 + mi * 16 + r;
                #pragma unroll
                for (int ni = 0; ni < 4; ni++) {
                    const int gq = wn * 32 + ni * 8 + c2;
                    float* o = ob + gm * DOUT + gq;
                    *(float2*)o = make_float2(acc[mi][ni][0], acc[mi][ni][1]);
                    *(float2*)(o + 8 * DOUT) =
                        make_float2(acc[mi][ni][2], acc[mi][ni][3]);
                }
            }
        }

        __syncthreads();   // convert(t+1) visible; conv[t&1] free for reuse
        n_cur = n_next; n_next = n_next2;
    }
    cp_wait0();
}

// ---------------- launch ----------------
extern "C" void kernel_launch(void* const* d_in, const int* in_sizes, int n_in,
                              void* d_out, int out_size)
{
    const float*        x    = nullptr;
    const unsigned int* sidx = nullptr;
    const float*        W    = nullptr;
    for (int i = 0; i < n_in; i++) {
        if      (in_sizes[i] == NSAMP * NCOMP * DIN) x    = (const float*)d_in[i];
        else if (in_sizes[i] == NSAMP)               sidx = (const unsigned int*)d_in[i];
        else if (in_sizes[i] == NSPEC * DIN * DOUT)  W    = (const float*)d_in[i];
    }
    float* out = (float*)d_out;

    prep0_detect<<<1, 256>>>(sidx);
    prep1_decode_count<<<NSAMP / 256, 256>>>(sidx);
    prep2_offsets<<<1, 1>>>();
    prep3_scatter<<<NSAMP / 256, 256>>>();
    prep4_wimg<<<NSPEC, 256>>>(W);

    cudaFuncSetAttribute(mma_main, cudaFuncAttributeMaxDynamicSharedMemorySize,
                         SM_TOTAL);
    mma_main<<<GRIDSZ, 256, SM_TOTAL>>>(x, out);
}

// round 9
// speedup vs baseline: 1.1923x; 1.0527x over previous
#include <cuda_runtime.h>
#include <cstdint>

// out[n,m,q] = sum_d x[n,m,d] * W[sidx[n],d,q]
// x: [16384,64,128] f32, sidx: [16384] i32/i64, W: [8,128,128] f32
// Route: species-grouped persistent CTAs + mma.sync.m16n8k16 bf16 3-term
// fp32 emulation. Conversion of sample t+1 is FUSED into the MMA k-loop of
// sample t (1/8 chunk per k-step) so ALU convert work hides in HMMA slots.

#define NSAMP  16384
#define NCOMP  64
#define DIN    128
#define DOUT   128
#define NSPEC  8
#define SLOTS  19
#define GRIDSZ (NSPEC * SLOTS)     // 152 = GB300 SM count

#define KPAD   136                 // padded k-stride (bank-rotation 4i mod 32)
#define WELEMS (DOUT * KPAD)       // 17408 bf16 per W image
#define CONVB  (NCOMP * KPAD * 2)  // 17408 B: one xhi (or xlo) image

// ---------------- device scratch ----------------
__device__ int g_sidx[NSAMP];
__device__ int g_cnt[NSPEC];
__device__ int g_off[NSPEC];
__device__ int g_fill[NSPEC];
__device__ int g_sorted[NSAMP];
__device__ int g_is64;
__device__ __align__(16) uint16_t g_whi[NSPEC][WELEMS];  // Wt[q][k] bf16 hi
__device__ __align__(16) uint16_t g_wlo[NSPEC][WELEMS];  // Wt[q][k] bf16 lo

// ---------------- smem layout (bytes) ----------------
#define SM_WHI   0
#define SM_WLO   (SM_WHI + WELEMS * 2)        // 34816
#define SM_CONV0 (SM_WLO + WELEMS * 2)        // 69632  (xhi0 | xlo0)
#define SM_CONV1 (SM_CONV0 + 2 * CONVB)       // 104448 (xhi1 | xlo1)
#define SM_RAW0  (SM_CONV1 + 2 * CONVB)       // 139264
#define SM_RAW1  (SM_RAW0 + 32768)            // 172032
#define SM_TOTAL (SM_RAW1 + 32768)            // 204800

// ---------------- PTX helpers ----------------
__device__ __forceinline__ uint32_t smem_u32(const void* p) {
    uint32_t a;
    asm("{ .reg .u64 t; cvta.to.shared.u64 t, %1; cvt.u32.u64 %0, t; }"
        : "=r"(a) : "l"(p));
    return a;
}
__device__ __forceinline__ void cp16(uint32_t dst, const void* src) {
    asm volatile("cp.async.cg.shared.global [%0], [%1], 16;"
                 :: "r"(dst), "l"(src) : "memory");
}
__device__ __forceinline__ void cp_commit() {
    asm volatile("cp.async.commit_group;" ::: "memory");
}
__device__ __forceinline__ void cp_wait0() {
    asm volatile("cp.async.wait_group 0;" ::: "memory");
}
__device__ __forceinline__ void cp_wait1() {
    asm volatile("cp.async.wait_group 1;" ::: "memory");
}
__device__ __forceinline__ void ldsm4(uint32_t* r, uint32_t addr) {
    asm volatile("ldmatrix.sync.aligned.m8n8.x4.shared.b16 {%0,%1,%2,%3}, [%4];"
                 : "=r"(r[0]), "=r"(r[1]), "=r"(r[2]), "=r"(r[3]) : "r"(addr));
}
__device__ __forceinline__ void mma_bf16(float* d, const uint32_t* a,
                                         const uint32_t* b) {
    asm volatile(
        "mma.sync.aligned.m16n8k16.row.col.f32.bf16.bf16.f32 "
        "{%0,%1,%2,%3}, {%4,%5,%6,%7}, {%8,%9}, {%0,%1,%2,%3};"
        : "+f"(d[0]), "+f"(d[1]), "+f"(d[2]), "+f"(d[3])
        : "r"(a[0]), "r"(a[1]), "r"(a[2]), "r"(a[3]), "r"(b[0]), "r"(b[1]));
}
__device__ __forceinline__ uint32_t pack_bf16x2(float fh, float fl) {
    uint32_t r;
    asm("cvt.rn.bf16x2.f32 %0, %1, %2;" : "=r"(r) : "f"(fh), "f"(fl));
    return r;
}
__device__ __forceinline__ uint32_t prmt7632(uint32_t a, uint32_t b) {
    uint32_t r;
    asm("prmt.b32 %0, %1, %2, 0x7632;" : "=r"(r) : "r"(a), "r"(b));
    return r;
}

// ---------------- prep kernels (proven R2-R6) ----------------
__global__ void prep0_detect(const unsigned int* __restrict__ raw) {
    __shared__ int s_not64;
    int tid = threadIdx.x;
    if (tid == 0) s_not64 = 0;
    if (tid < NSPEC) { g_cnt[tid] = 0; g_fill[tid] = 0; }
    __syncthreads();
    int bad = 0;
    for (int w = tid * 2 + 1; w < NSAMP; w += 512)
        if (raw[w] != 0u) bad = 1;
    if (bad) atomicOr(&s_not64, 1);
    __syncthreads();
    if (tid == 0) g_is64 = (s_not64 == 0);
}
__global__ void prep1_decode_count(const unsigned int* __restrict__ raw) {
    int i = blockIdx.x * 256 + threadIdx.x;
    unsigned v = g_is64 ? raw[2 * i] : raw[i];
    if (v > 7u) v = 7u;
    g_sidx[i] = (int)v;
    atomicAdd(&g_cnt[v], 1);
}
__global__ void prep2_offsets() {
    int o = 0;
    for (int s = 0; s < NSPEC; s++) { g_off[s] = o; o += g_cnt[s]; }
}
__global__ void prep3_scatter() {
    int n = blockIdx.x * 256 + threadIdx.x;
    int s = g_sidx[n];
    int pos = atomicAdd(&g_fill[s], 1);
    g_sorted[g_off[s] + pos] = n;
}
__global__ void prep4_wimg(const float* __restrict__ W) {
    int s = blockIdx.x;
    for (int e = threadIdx.x; e < WELEMS; e += blockDim.x) {
        int q = e / KPAD, k = e % KPAD;
        uint16_t hb = 0, lb = 0;
        if (k < DIN) {
            float v = W[s * DIN * DOUT + k * DOUT + q];
            uint32_t p = pack_bf16x2(v, 0.0f);           // RN hi for W
            hb = (uint16_t)(p >> 16);
            float hf = __uint_as_float(((uint32_t)hb) << 16);
            uint32_t pl = pack_bf16x2(v - hf, 0.0f);
            lb = (uint16_t)(pl >> 16);
        }
        g_whi[s][q * KPAD + k] = hb;
        g_wlo[s][q * KPAD + k] = lb;
    }
}

// ---------------- conversion chunk: 1024 floats (4 per thread) ------------
// hi = RZ truncation (prmt-packed), lo = rn(v - hi).
__device__ __forceinline__ void convert_chunk(char* smem, int rawOff,
                                              int convOff, int tid, int jj)
{
    const int f   = jj * 1024 + tid * 4;
    const int row = f >> 7;
    const int k   = f & 127;
    const uint4 b = *(const uint4*)((const char*)smem + rawOff + f * 4);

    uint32_t h01 = prmt7632(b.x, b.y);
    uint32_t h23 = prmt7632(b.z, b.w);
    float s0 = __uint_as_float(b.x) - __uint_as_float(b.x & 0xFFFF0000u);
    float s1 = __uint_as_float(b.y) - __uint_as_float(b.y & 0xFFFF0000u);
    float s2 = __uint_as_float(b.z) - __uint_as_float(b.z & 0xFFFF0000u);
    float s3 = __uint_as_float(b.w) - __uint_as_float(b.w & 0xFFFF0000u);
    uint32_t l01 = pack_bf16x2(s1, s0);
    uint32_t l23 = pack_bf16x2(s3, s2);

    const int boff = (row * KPAD + k) * 2;
    *(uint2*)(smem + convOff + boff)         = make_uint2(h01, h23);
    *(uint2*)(smem + convOff + CONVB + boff) = make_uint2(l01, l23);
}

// ---------------- main kernel ----------------
__global__ __launch_bounds__(256, 1)
void mma_main(const float* __restrict__ x, float* __restrict__ out)
{
    extern __shared__ char smem[];
    const uint32_t sb = smem_u32(smem);
    const int tid  = threadIdx.x;
    const int lane = tid & 31;
    const int wid  = tid >> 5;
    const int wm   = wid >> 2;           // 0..1  (m tile 32)
    const int wn   = wid & 3;            // 0..3  (n tile 32)
    const int spec = blockIdx.x / SLOTS;
    const int slot = blockIdx.x % SLOTS;

    // ---- stage W images (hi+lo bf16, 68 KB) once ----
    {
        const uint16_t* whi = g_whi[spec];
        const uint16_t* wlo = g_wlo[spec];
        #pragma unroll
        for (int i = 0; i < 9; i++) {
            int idx = tid + i * 256;
            if (idx < WELEMS / 8) {
                cp16(sb + SM_WHI + idx * 16, whi + idx * 8);
                cp16(sb + SM_WLO + idx * 16, wlo + idx * 8);
            }
        }
        cp_commit();
    }

    const int cnt = g_cnt[spec];
    const int off = g_off[spec];
    if (slot >= cnt) { cp_wait0(); return; }

    const int T = (cnt - slot + SLOTS - 1) / SLOTS;

    // ldmatrix lane address components
    const int a_row  = (lane & 15);
    const int a_koff = (lane >> 4) * 8;
    const int b_row  = ((lane >> 4) * 8) + (lane & 7);
    const int b_koff = ((lane >> 3) & 1) * 8;

    uint32_t aOff[2];                    // relative to conv buffer base (xhi)
    #pragma unroll
    for (int mi = 0; mi < 2; mi++)
        aOff[mi] = ((wm * 32 + mi * 16 + a_row) * KPAD + a_koff) * 2;
    uint32_t bAddr[2];
    #pragma unroll
    for (int p = 0; p < 2; p++)
        bAddr[p] = sb + SM_WHI + ((wn * 32 + p * 16 + b_row) * KPAD + b_koff) * 2;
    const uint32_t WLO_OFF = SM_WLO - SM_WHI;

    // ---- prologue: raw(n0) -> RAW0, raw(n1) -> RAW1, convert n0 ----
    int n0 = g_sorted[off + slot];
    int n1 = (slot + SLOTS < cnt) ? g_sorted[off + slot + SLOTS] : n0;
    {
        const float* xs = x + (size_t)n0 * (NCOMP * DIN);
        #pragma unroll
        for (int i = 0; i < 8; i++)
            cp16(sb + SM_RAW0 + (tid + i * 256) * 16, xs + (tid + i * 256) * 4);
        cp_commit();
        const float* xs1 = x + (size_t)n1 * (NCOMP * DIN);
        #pragma unroll
        for (int i = 0; i < 8; i++)
            cp16(sb + SM_RAW1 + (tid + i * 256) * 16, xs1 + (tid + i * 256) * 4);
        cp_commit();
    }
    cp_wait1();                          // W + raw(n0) complete
    #pragma unroll
    for (int jj = 0; jj < 8; jj++)
        convert_chunk(smem, SM_RAW0, SM_CONV0, tid, jj);
    __syncthreads();

    int n_cur = n0, n_next = n1;

    for (int t = 0; t < T; t++) {
        // cp.async sample t+2 into raw[t&1]
        const int i2 = off + slot + (t + 2) * SLOTS;
        const int n_next2 = (slot + (t + 2) * SLOTS < cnt) ? g_sorted[i2] : n_next;
        {
            const uint32_t dst = sb + ((t & 1) ? SM_RAW1 : SM_RAW0);
            const float* xs = x + (size_t)n_next2 * (NCOMP * DIN);
            #pragma unroll
            for (int i = 0; i < 8; i++)
                cp16(dst + (tid + i * 256) * 16, xs + (tid + i * 256) * 4);
            cp_commit();
        }
        cp_wait1();                      // raw(t+1) resident

        const int rawN  = (t & 1) ? SM_RAW0 : SM_RAW1;     // sample t+1 raw
        const int convN = ((t + 1) & 1) ? SM_CONV1 : SM_CONV0;
        const uint32_t xb = sb + ((t & 1) ? SM_CONV1 : SM_CONV0);

        float acc[2][4][4];
        #pragma unroll
        for (int mi = 0; mi < 2; mi++)
            #pragma unroll
            for (int ni = 0; ni < 4; ni++)
                #pragma unroll
                for (int e = 0; e < 4; e++) acc[mi][ni][e] = 0.0f;

        // ---- fused loop: MMA(t) k-step ks  +  convert(t+1) chunk ks ----
        #pragma unroll
        for (int ks = 0; ks < 8; ks++) {
            const uint32_t kb = ks * 32;
            uint32_t AH[2][4], AL[2][4], BH[2][4], BL[2][4];
            #pragma unroll
            for (int mi = 0; mi < 2; mi++) {
                ldsm4(AH[mi], xb + aOff[mi] + kb);
                ldsm4(AL[mi], xb + CONVB + aOff[mi] + kb);
            }
            #pragma unroll
            for (int p = 0; p < 2; p++) {
                ldsm4(BH[p], bAddr[p] + kb);
                ldsm4(BL[p], bAddr[p] + WLO_OFF + kb);
            }

            // convert chunk (independent of fragments; fills HMMA dead slots)
            convert_chunk(smem, rawN, convN, tid, ks);

            #pragma unroll
            for (int mi = 0; mi < 2; mi++)
                #pragma unroll
                for (int p = 0; p < 2; p++)
                    #pragma unroll
                    for (int h = 0; h < 2; h++) {
                        const int ni = p * 2 + h;
                        mma_bf16(acc[mi][ni], AH[mi], &BH[p][2 * h]);
                        mma_bf16(acc[mi][ni], AH[mi], &BL[p][2 * h]);
                        mma_bf16(acc[mi][ni], AL[mi], &BH[p][2 * h]);
                    }
        }

        // ---- epilogue: direct STG.64 for sample t ----
        {
            const int r  = lane >> 2;
            const int c2 = 2 * (lane & 3);
            float* ob = out + (size_t)n_cur * (NCOMP * DOUT);
            #pragma unroll
            for (int mi = 0; mi < 2; mi++) {
                const int gm = wm * 32 + mi * 16 + r;
                #pragma unroll
                for (int ni = 0; ni < 4; ni++) {
                    const int gq = wn * 32 + ni * 8 + c2;
                    float* o = ob + gm * DOUT + gq;
                    *(float2*)o = make_float2(acc[mi][ni][0], acc[mi][ni][1]);
                    *(float2*)(o + 8 * DOUT) =
                        make_float2(acc[mi][ni][2], acc[mi][ni][3]);
                }
            }
        }

        __syncthreads();   // convert(t+1) visible; buffers rotate
        n_cur = n_next; n_next = n_next2;
    }
    cp_wait0();
}

// ---------------- launch ----------------
extern "C" void kernel_launch(void* const* d_in, const int* in_sizes, int n_in,
                              void* d_out, int out_size)
{
    const float*        x    = nullptr;
    const unsigned int* sidx = nullptr;
    const float*        W    = nullptr;
    for (int i = 0; i < n_in; i++) {
        if      (in_sizes[i] == NSAMP * NCOMP * DIN) x    = (const float*)d_in[i];
        else if (in_sizes[i] == NSAMP)               sidx = (const unsigned int*)d_in[i];
        else if (in_sizes[i] == NSPEC * DIN * DOUT)  W    = (const float*)d_in[i];
    }
    float* out = (float*)d_out;

    prep0_detect<<<1, 256>>>(sidx);
    prep1_decode_count<<<NSAMP / 256, 256>>>(sidx);
    prep2_offsets<<<1, 1>>>();
    prep3_scatter<<<NSAMP / 256, 256>>>();
    prep4_wimg<<<NSPEC, 256>>>(W);

    cudaFuncSetAttribute(mma_main, cudaFuncAttributeMaxDynamicSharedMemorySize,
                         SM_TOTAL);
    mma_main<<<GRIDSZ, 256, SM_TOTAL>>>(x, out);
}

// round 10
// speedup vs baseline: 1.7639x; 1.4794x over previous
#include <cuda_runtime.h>
#include <cstdint>

// out[n,m,q] = sum_d x[n,m,d] * W[sidx[n],d,q]
// x: [16384,64,128] f32, sidx: [16384] i32/i64, W: [8,128,128] f32
// Route: species-grouped persistent CTAs + SINGLE-term fp16 mma.sync
// (m16n8k16). x and W rounded RN to fp16; unbiased error ~2.8e-4 << 1e-3.
// 17.2 G MAC -> memory-bound (~134 us DRAM floor).

#define NSAMP  16384
#define NCOMP  64
#define DIN    128
#define DOUT   128
#define NSPEC  8
#define SLOTS  19
#define GRIDSZ (NSPEC * SLOTS)     // 152 = GB300 SM count

#define KPAD   136                 // padded k-stride (bank-rotation 4i mod 32)
#define WELEMS (DOUT * KPAD)       // 17408 fp16 per W image
#define CONVB  (NCOMP * KPAD * 2)  // 17408 B: one x fp16 image

// ---------------- device scratch ----------------
__device__ int g_sidx[NSAMP];
__device__ int g_cnt[NSPEC];
__device__ int g_off[NSPEC];
__device__ int g_fill[NSPEC];
__device__ int g_sorted[NSAMP];
__device__ int g_is64;
__device__ __align__(16) uint16_t g_wh[NSPEC][WELEMS];   // Wt[q][k] fp16 RN

// ---------------- smem layout (bytes) ----------------
#define SM_W     0
#define SM_CONV  (SM_W + WELEMS * 2)          // 34816
#define SM_RAW0  (SM_CONV + CONVB)            // 52224
#define SM_RAW1  (SM_RAW0 + 32768)            // 84992
#define SM_TOTAL (SM_RAW1 + 32768)            // 117760

// ---------------- PTX helpers ----------------
__device__ __forceinline__ uint32_t smem_u32(const void* p) {
    uint32_t a;
    asm("{ .reg .u64 t; cvta.to.shared.u64 t, %1; cvt.u32.u64 %0, t; }"
        : "=r"(a) : "l"(p));
    return a;
}
__device__ __forceinline__ void cp16(uint32_t dst, const void* src) {
    asm volatile("cp.async.cg.shared.global [%0], [%1], 16;"
                 :: "r"(dst), "l"(src) : "memory");
}
__device__ __forceinline__ void cp_commit() {
    asm volatile("cp.async.commit_group;" ::: "memory");
}
__device__ __forceinline__ void cp_wait0() {
    asm volatile("cp.async.wait_group 0;" ::: "memory");
}
__device__ __forceinline__ void cp_wait1() {
    asm volatile("cp.async.wait_group 1;" ::: "memory");
}
__device__ __forceinline__ void ldsm4(uint32_t* r, uint32_t addr) {
    asm volatile("ldmatrix.sync.aligned.m8n8.x4.shared.b16 {%0,%1,%2,%3}, [%4];"
                 : "=r"(r[0]), "=r"(r[1]), "=r"(r[2]), "=r"(r[3]) : "r"(addr));
}
__device__ __forceinline__ void mma_f16(float* d, const uint32_t* a,
                                        const uint32_t* b) {
    asm volatile(
        "mma.sync.aligned.m16n8k16.row.col.f32.f16.f16.f32 "
        "{%0,%1,%2,%3}, {%4,%5,%6,%7}, {%8,%9}, {%0,%1,%2,%3};"
        : "+f"(d[0]), "+f"(d[1]), "+f"(d[2]), "+f"(d[3])
        : "r"(a[0]), "r"(a[1]), "r"(a[2]), "r"(a[3]), "r"(b[0]), "r"(b[1]));
}
// packs {upper = fh, lower = fl} (little-endian: fl at lower address)
__device__ __forceinline__ uint32_t pack_f16x2(float fh, float fl) {
    uint32_t r;
    asm("cvt.rn.f16x2.f32 %0, %1, %2;" : "=r"(r) : "f"(fh), "f"(fl));
    return r;
}

// ---------------- prep kernels (decode/group proven R2-R9) ----------------
__global__ void prep0_detect(const unsigned int* __restrict__ raw) {
    __shared__ int s_not64;
    int tid = threadIdx.x;
    if (tid == 0) s_not64 = 0;
    if (tid < NSPEC) { g_cnt[tid] = 0; g_fill[tid] = 0; }
    __syncthreads();
    int bad = 0;
    for (int w = tid * 2 + 1; w < NSAMP; w += 512)
        if (raw[w] != 0u) bad = 1;
    if (bad) atomicOr(&s_not64, 1);
    __syncthreads();
    if (tid == 0) g_is64 = (s_not64 == 0);
}
__global__ void prep1_decode_count(const unsigned int* __restrict__ raw) {
    int i = blockIdx.x * 256 + threadIdx.x;
    unsigned v = g_is64 ? raw[2 * i] : raw[i];
    if (v > 7u) v = 7u;
    g_sidx[i] = (int)v;
    atomicAdd(&g_cnt[v], 1);
}
__global__ void prep2_offsets() {
    int o = 0;
    for (int s = 0; s < NSPEC; s++) { g_off[s] = o; o += g_cnt[s]; }
}
__global__ void prep3_scatter() {
    int n = blockIdx.x * 256 + threadIdx.x;
    int s = g_sidx[n];
    int pos = atomicAdd(&g_fill[s], 1);
    g_sorted[g_off[s] + pos] = n;
}
// Wt[q][k] fp16 RN, padded to KPAD (pads zero).
__global__ void prep4_wimg(const float* __restrict__ W) {
    int s = blockIdx.x;
    for (int e = threadIdx.x; e < WELEMS; e += blockDim.x) {
        int q = e / KPAD, k = e % KPAD;
        uint16_t hb = 0;
        if (k < DIN) {
            float v = W[s * DIN * DOUT + k * DOUT + q];
            hb = (uint16_t)(pack_f16x2(v, 0.0f) >> 16);
        }
        g_wh[s][q * KPAD + k] = hb;
    }
}

// ---------------- main kernel ----------------
__global__ __launch_bounds__(256, 1)
void mma_main(const float* __restrict__ x, float* __restrict__ out)
{
    extern __shared__ char smem[];
    const uint32_t sb = smem_u32(smem);
    const int tid  = threadIdx.x;
    const int lane = tid & 31;
    const int wid  = tid >> 5;
    const int wm   = wid >> 2;           // 0..1  (m tile 32)
    const int wn   = wid & 3;            // 0..3  (n tile 32)
    const int spec = blockIdx.x / SLOTS;
    const int slot = blockIdx.x % SLOTS;

    // ---- stage W image (fp16, 34 KB) once ----
    {
        const uint16_t* wh = g_wh[spec];
        #pragma unroll
        for (int i = 0; i < 9; i++) {
            int idx = tid + i * 256;
            if (idx < WELEMS / 8)
                cp16(sb + SM_W + idx * 16, wh + idx * 8);
        }
        cp_commit();
    }

    const int cnt = g_cnt[spec];
    const int off = g_off[spec];
    if (slot >= cnt) { cp_wait0(); return; }

    // ldmatrix lane address components
    const int a_row  = (lane & 15);
    const int a_koff = (lane >> 4) * 8;
    const int b_row  = ((lane >> 4) * 8) + (lane & 7);
    const int b_koff = ((lane >> 3) & 1) * 8;

    uint32_t aAddr[2];
    #pragma unroll
    for (int mi = 0; mi < 2; mi++)
        aAddr[mi] = sb + SM_CONV +
            ((wm * 32 + mi * 16 + a_row) * KPAD + a_koff) * 2;
    uint32_t bAddr[2];
    #pragma unroll
    for (int p = 0; p < 2; p++)
        bAddr[p] = sb + SM_W +
            ((wn * 32 + p * 16 + b_row) * KPAD + b_koff) * 2;

    // ---- prefetch first sample ----
    int n_cur = g_sorted[off + slot];
    {
        const float* xs = x + (size_t)n_cur * (NCOMP * DIN);
        #pragma unroll
        for (int i = 0; i < 8; i++)
            cp16(sb + SM_RAW0 + (tid + i * 256) * 16, xs + (tid + i * 256) * 4);
        cp_commit();
    }

    int buf = 0;
    for (int j = slot; j < cnt; j += SLOTS) {
        const int jn = j + SLOTS;
        const int n_next = (jn < cnt) ? g_sorted[off + jn] : n_cur;
        {
            const uint32_t dst = sb + (buf ? SM_RAW0 : SM_RAW1);
            const float* xs = x + (size_t)n_next * (NCOMP * DIN);
            #pragma unroll
            for (int i = 0; i < 8; i++)
                cp16(dst + (tid + i * 256) * 16, xs + (tid + i * 256) * 4);
            cp_commit();
        }
        cp_wait1();                  // current raw buffer complete
        __syncthreads();             // prev MMA's reads of SM_CONV done

        // ---- convert raw fp32 -> fp16 image (cheap: ~40 instr/thread) ----
        {
            const float* rawf = (const float*)(smem + (buf ? SM_RAW1 : SM_RAW0));
            #pragma unroll
            for (int jj = 0; jj < 8; jj++) {
                const int f   = jj * 1024 + tid * 4;
                const int row = f >> 7;
                const int k   = f & 127;
                float4 v = *(const float4*)(rawf + f);
                uint32_t h01 = pack_f16x2(v.y, v.x);
                uint32_t h23 = pack_f16x2(v.w, v.z);
                *(uint2*)(smem + SM_CONV + (row * KPAD + k) * 2) =
                    make_uint2(h01, h23);
            }
        }
        __syncthreads();

        // ---- single-term fp16 mma over K=128 ----
        float acc[2][4][4];
        #pragma unroll
        for (int mi = 0; mi < 2; mi++)
            #pragma unroll
            for (int ni = 0; ni < 4; ni++)
                #pragma unroll
                for (int e = 0; e < 4; e++) acc[mi][ni][e] = 0.0f;

        #pragma unroll
        for (int ks = 0; ks < 8; ks++) {
            const uint32_t kb = ks * 32;
            uint32_t A[2][4], B[2][4];
            #pragma unroll
            for (int mi = 0; mi < 2; mi++)
                ldsm4(A[mi], aAddr[mi] + kb);
            #pragma unroll
            for (int p = 0; p < 2; p++)
                ldsm4(B[p], bAddr[p] + kb);
            #pragma unroll
            for (int mi = 0; mi < 2; mi++)
                #pragma unroll
                for (int p = 0; p < 2; p++)
                    #pragma unroll
                    for (int h = 0; h < 2; h++)
                        mma_f16(acc[mi][p * 2 + h], A[mi], &B[p][2 * h]);
        }

        // ---- epilogue: direct STG.64 ----
        {
            const int r  = lane >> 2;
            const int c2 = 2 * (lane & 3);
            float* ob = out + (size_t)n_cur * (NCOMP * DOUT);
            #pragma unroll
            for (int mi = 0; mi < 2; mi++) {
                const int gm = wm * 32 + mi * 16 + r;
                #pragma unroll
                for (int ni = 0; ni < 4; ni++) {
                    const int gq = wn * 32 + ni * 8 + c2;
                    float* o = ob + gm * DOUT + gq;
                    *(float2*)o = make_float2(acc[mi][ni][0], acc[mi][ni][1]);
                    *(float2*)(o + 8 * DOUT) =
                        make_float2(acc[mi][ni][2], acc[mi][ni][3]);
                }
            }
        }

        n_cur = n_next;
        buf ^= 1;
    }
    cp_wait0();
}

// ---------------- launch ----------------
extern "C" void kernel_launch(void* const* d_in, const int* in_sizes, int n_in,
                              void* d_out, int out_size)
{
    const float*        x    = nullptr;
    const unsigned int* sidx = nullptr;
    const float*        W    = nullptr;
    for (int i = 0; i < n_in; i++) {
        if      (in_sizes[i] == NSAMP * NCOMP * DIN) x    = (const float*)d_in[i];
        else if (in_sizes[i] == NSAMP)               sidx = (const unsigned int*)d_in[i];
        else if (in_sizes[i] == NSPEC * DIN * DOUT)  W    = (const float*)d_in[i];
    }
    float* out = (float*)d_out;

    prep0_detect<<<1, 256>>>(sidx);
    prep1_decode_count<<<NSAMP / 256, 256>>>(sidx);
    prep2_offsets<<<1, 1>>>();
    prep3_scatter<<<NSAMP / 256, 256>>>();
    prep4_wimg<<<NSPEC, 256>>>(W);

    cudaFuncSetAttribute(mma_main, cudaFuncAttributeMaxDynamicSharedMemorySize,
                         SM_TOTAL);
    mma_main<<<GRIDSZ, 256, SM_TOTAL>>>(x, out);
}

// round 11
// speedup vs baseline: 1.7845x; 1.0117x over previous
#include <cuda_runtime.h>
#include <cstdint>

// out[n,m,q] = sum_d x[n,m,d] * W[sidx[n],d,q]
// x: [16384,64,128] f32, sidx: [16384] i32/i64, W: [8,128,128] f32
// Route: species-grouped persistent CTAs + single-term fp16 mma.sync.
// LDG-direct x path (no raw smem staging): prefetch sample t+1 into regs
// before MMA(t), convert regs->fp16 smem after epilogue. 68 KB smem ->
// 2 CTAs/SM so one CTA's MMA hides the other's convert phase.

#define NSAMP  16384
#define NCOMP  64
#define DIN    128
#define DOUT   128
#define NSPEC  8
#define SLOTS  38                  // 2 CTAs/SM * 19
#define GRIDSZ (NSPEC * SLOTS)     // 304 = 2 * 152 SMs

#define KPAD   136                 // padded k-stride (bank-rotation 4i mod 32)
#define WELEMS (DOUT * KPAD)       // 17408 fp16 per W image
#define CONVB  (NCOMP * KPAD * 2)  // 17408 B: one x fp16 image

// ---------------- device scratch ----------------
__device__ int g_sidx[NSAMP];
__device__ int g_cnt[NSPEC];
__device__ int g_off[NSPEC];
__device__ int g_fill[NSPEC];
__device__ int g_sorted[NSAMP];
__device__ int g_is64;
__device__ __align__(16) uint16_t g_wh[NSPEC][WELEMS];   // Wt[q][k] fp16 RN

// ---------------- smem layout (bytes) ----------------
#define SM_W     0
#define SM_CONV0 (SM_W + WELEMS * 2)          // 34816
#define SM_CONV1 (SM_CONV0 + CONVB)           // 52224
#define SM_TOTAL (SM_CONV1 + CONVB)           // 69632

// ---------------- PTX helpers ----------------
__device__ __forceinline__ uint32_t smem_u32(const void* p) {
    uint32_t a;
    asm("{ .reg .u64 t; cvta.to.shared.u64 t, %1; cvt.u32.u64 %0, t; }"
        : "=r"(a) : "l"(p));
    return a;
}
__device__ __forceinline__ void cp16(uint32_t dst, const void* src) {
    asm volatile("cp.async.cg.shared.global [%0], [%1], 16;"
                 :: "r"(dst), "l"(src) : "memory");
}
__device__ __forceinline__ void cp_commit() {
    asm volatile("cp.async.commit_group;" ::: "memory");
}
__device__ __forceinline__ void cp_wait0() {
    asm volatile("cp.async.wait_group 0;" ::: "memory");
}
__device__ __forceinline__ void ldsm4(uint32_t* r, uint32_t addr) {
    asm volatile("ldmatrix.sync.aligned.m8n8.x4.shared.b16 {%0,%1,%2,%3}, [%4];"
                 : "=r"(r[0]), "=r"(r[1]), "=r"(r[2]), "=r"(r[3]) : "r"(addr));
}
__device__ __forceinline__ void mma_f16(float* d, const uint32_t* a,
                                        const uint32_t* b) {
    asm volatile(
        "mma.sync.aligned.m16n8k16.row.col.f32.f16.f16.f32 "
        "{%0,%1,%2,%3}, {%4,%5,%6,%7}, {%8,%9}, {%0,%1,%2,%3};"
        : "+f"(d[0]), "+f"(d[1]), "+f"(d[2]), "+f"(d[3])
        : "r"(a[0]), "r"(a[1]), "r"(a[2]), "r"(a[3]), "r"(b[0]), "r"(b[1]));
}
// packs {upper = fh, lower = fl}
__device__ __forceinline__ uint32_t pack_f16x2(float fh, float fl) {
    uint32_t r;
    asm("cvt.rn.f16x2.f32 %0, %1, %2;" : "=r"(r) : "f"(fh), "f"(fl));
    return r;
}

// ---------------- prep kernels (proven R2-R10) ----------------
__global__ void prep0_detect(const unsigned int* __restrict__ raw) {
    __shared__ int s_not64;
    int tid = threadIdx.x;
    if (tid == 0) s_not64 = 0;
    if (tid < NSPEC) { g_cnt[tid] = 0; g_fill[tid] = 0; }
    __syncthreads();
    int bad = 0;
    for (int w = tid * 2 + 1; w < NSAMP; w += 512)
        if (raw[w] != 0u) bad = 1;
    if (bad) atomicOr(&s_not64, 1);
    __syncthreads();
    if (tid == 0) g_is64 = (s_not64 == 0);
}
__global__ void prep1_decode_count(const unsigned int* __restrict__ raw) {
    int i = blockIdx.x * 256 + threadIdx.x;
    unsigned v = g_is64 ? raw[2 * i] : raw[i];
    if (v > 7u) v = 7u;
    g_sidx[i] = (int)v;
    atomicAdd(&g_cnt[v], 1);
}
__global__ void prep2_offsets() {
    int o = 0;
    for (int s = 0; s < NSPEC; s++) { g_off[s] = o; o += g_cnt[s]; }
}
__global__ void prep3_scatter() {
    int n = blockIdx.x * 256 + threadIdx.x;
    int s = g_sidx[n];
    int pos = atomicAdd(&g_fill[s], 1);
    g_sorted[g_off[s] + pos] = n;
}
__global__ void prep4_wimg(const float* __restrict__ W) {
    int s = blockIdx.x;
    for (int e = threadIdx.x; e < WELEMS; e += blockDim.x) {
        int q = e / KPAD, k = e % KPAD;
        uint16_t hb = 0;
        if (k < DIN) {
            float v = W[s * DIN * DOUT + k * DOUT + q];
            hb = (uint16_t)(pack_f16x2(v, 0.0f) >> 16);
        }
        g_wh[s][q * KPAD + k] = hb;
    }
}

// ---------------- main kernel ----------------
__global__ __launch_bounds__(256, 2)
void mma_main(const float* __restrict__ x, float* __restrict__ out)
{
    extern __shared__ char smem[];
    const uint32_t sb = smem_u32(smem);
    const int tid  = threadIdx.x;
    const int lane = tid & 31;
    const int wid  = tid >> 5;
    const int wm   = wid >> 2;           // 0..1  (m tile 32)
    const int wn   = wid & 3;            // 0..3  (n tile 32)
    const int spec = blockIdx.x / SLOTS;
    const int slot = blockIdx.x % SLOTS;

    // ---- stage W image (fp16, 34 KB) once via cp.async ----
    {
        const uint16_t* wh = g_wh[spec];
        #pragma unroll
        for (int i = 0; i < 9; i++) {
            int idx = tid + i * 256;
            if (idx < WELEMS / 8)
                cp16(sb + SM_W + idx * 16, wh + idx * 8);
        }
        cp_commit();
    }

    const int cnt = g_cnt[spec];
    const int off = g_off[spec];
    if (slot >= cnt) { cp_wait0(); return; }

    // ldmatrix lane address components
    const int a_row  = (lane & 15);
    const int a_koff = (lane >> 4) * 8;
    const int b_row  = ((lane >> 4) * 8) + (lane & 7);
    const int b_koff = ((lane >> 3) & 1) * 8;

    uint32_t aOff[2];                    // relative to conv buffer
    #pragma unroll
    for (int mi = 0; mi < 2; mi++)
        aOff[mi] = ((wm * 32 + mi * 16 + a_row) * KPAD + a_koff) * 2;
    uint32_t bAddr[2];
    #pragma unroll
    for (int p = 0; p < 2; p++)
        bAddr[p] = sb + SM_W +
            ((wn * 32 + p * 16 + b_row) * KPAD + b_koff) * 2;

    // per-thread conv-store geometry: thread covers float4 idx tid+i*256
    // idx -> row = idx>>5, c16 = idx&31 (float4 within row)
    // conv byte offset = (row*KPAD + c16*4)*2
    uint32_t cOff[8];
    #pragma unroll
    for (int i = 0; i < 8; i++) {
        const int idx = tid + i * 256;
        cOff[i] = (uint32_t)(((idx >> 5) * KPAD + (idx & 31) * 4) * 2);
    }

    // ---- prologue: LDG sample 0, convert into CONV0 ----
    int n_cur = g_sorted[off + slot];
    float4 xr[8];
    {
        const float4* xg = (const float4*)(x + (size_t)n_cur * (NCOMP * DIN));
        #pragma unroll
        for (int i = 0; i < 8; i++) xr[i] = xg[tid + i * 256];
    }
    cp_wait0();                          // W resident
    #pragma unroll
    for (int i = 0; i < 8; i++) {
        uint32_t h01 = pack_f16x2(xr[i].y, xr[i].x);
        uint32_t h23 = pack_f16x2(xr[i].w, xr[i].z);
        *(uint2*)(smem + SM_CONV0 + cOff[i]) = make_uint2(h01, h23);
    }
    __syncthreads();

    for (int j = slot, t = 0; j < cnt; j += SLOTS, t++) {
        // ---- prefetch sample t+1 into registers (hides under MMA) ----
        const int jn = j + SLOTS;
        const int n_next = (jn < cnt) ? g_sorted[off + jn] : n_cur;
        {
            const float4* xg =
                (const float4*)(x + (size_t)n_next * (NCOMP * DIN));
            #pragma unroll
            for (int i = 0; i < 8; i++) xr[i] = xg[tid + i * 256];
        }

        // ---- single-term fp16 mma on conv[t&1] ----
        const uint32_t xb = sb + ((t & 1) ? SM_CONV1 : SM_CONV0);
        float acc[2][4][4];
        #pragma unroll
        for (int mi = 0; mi < 2; mi++)
            #pragma unroll
            for (int ni = 0; ni < 4; ni++)
                #pragma unroll
                for (int e = 0; e < 4; e++) acc[mi][ni][e] = 0.0f;

        #pragma unroll
        for (int ks = 0; ks < 8; ks++) {
            const uint32_t kb = ks * 32;
            uint32_t A[2][4], B[2][4];
            #pragma unroll
            for (int mi = 0; mi < 2; mi++)
                ldsm4(A[mi], xb + aOff[mi] + kb);
            #pragma unroll
            for (int p = 0; p < 2; p++)
                ldsm4(B[p], bAddr[p] + kb);
            #pragma unroll
            for (int mi = 0; mi < 2; mi++)
                #pragma unroll
                for (int p = 0; p < 2; p++)
                    #pragma unroll
                    for (int h = 0; h < 2; h++)
                        mma_f16(acc[mi][p * 2 + h], A[mi], &B[p][2 * h]);
        }

        // ---- epilogue: direct STG.64 for sample t ----
        {
            const int r  = lane >> 2;
            const int c2 = 2 * (lane & 3);
            float* ob = out + (size_t)n_cur * (NCOMP * DOUT);
            #pragma unroll
            for (int mi = 0; mi < 2; mi++) {
                const int gm = wm * 32 + mi * 16 + r;
                #pragma unroll
                for (int ni = 0; ni < 4; ni++) {
                    const int gq = wn * 32 + ni * 8 + c2;
                    float* o = ob + gm * DOUT + gq;
                    *(float2*)o = make_float2(acc[mi][ni][0], acc[mi][ni][1]);
                    *(float2*)(o + 8 * DOUT) =
                        make_float2(acc[mi][ni][2], acc[mi][ni][3]);
                }
            }
        }

        // ---- convert regs(t+1) -> conv[(t+1)&1] ----
        {
            const uint32_t cb = (uint32_t)(size_t)(smem +
                (((t + 1) & 1) ? SM_CONV1 : SM_CONV0) - (char*)smem)
                + (((t + 1) & 1) ? SM_CONV1 : SM_CONV0) * 0;  // (kept simple below)
        }
        {
            char* cbuf = smem + (((t + 1) & 1) ? SM_CONV1 : SM_CONV0);
            #pragma unroll
            for (int i = 0; i < 8; i++) {
                uint32_t h01 = pack_f16x2(xr[i].y, xr[i].x);
                uint32_t h23 = pack_f16x2(xr[i].w, xr[i].z);
                *(uint2*)(cbuf + cOff[i]) = make_uint2(h01, h23);
            }
        }

        __syncthreads();   // conv(t+1) visible; conv[t&1] free next iter
        n_cur = n_next;
    }
}

// ---------------- launch ----------------
extern "C" void kernel_launch(void* const* d_in, const int* in_sizes, int n_in,
                              void* d_out, int out_size)
{
    const float*        x    = nullptr;
    const unsigned int* sidx = nullptr;
    const float*        W    = nullptr;
    for (int i = 0; i < n_in; i++) {
        if      (in_sizes[i] == NSAMP * NCOMP * DIN) x    = (const float*)d_in[i];
        else if (in_sizes[i] == NSAMP)               sidx = (const unsigned int*)d_in[i];
        else if (in_sizes[i] == NSPEC * DIN * DOUT)  W    = (const float*)d_in[i];
    }
    float* out = (float*)d_out;

    prep0_detect<<<1, 256>>>(sidx);
    prep1_decode_count<<<NSAMP / 256, 256>>>(sidx);
    prep2_offsets<<<1, 1>>>();
    prep3_scatter<<<NSAMP / 256, 256>>>();
    prep4_wimg<<<NSPEC, 256>>>(W);

    cudaFuncSetAttribute(mma_main, cudaFuncAttributeMaxDynamicSharedMemorySize,
                         SM_TOTAL);
    mma_main<<<GRIDSZ, 256, SM_TOTAL>>>(x, out);
}